// round 3
// baseline (speedup 1.0000x reference)
#include <cuda_runtime.h>
#include <math.h>

// ---------------- problem constants ----------------
#define NB   2048
#define KS   8
#define HID  256
#define IMG_HW 16384       // 128*128
#define GNUM 50

// padded strides (multiples of 16 for GEMM BK)
#define LD_G1   2512       // glimpse1 buffer (2500 real)
#define LD_XREL 720        // [enc100|zwl3|pzw3|zwhatl50|pzwhat50|hl256|h_r256] = 718 real
#define LD_XTEM 3120       // [g2 2500|zw3|pzw3|zwhatl50|pzwhat50|hl256|h_r2 256] = 3118 real

// xrel column offsets
#define XR_ENC 0
#define XR_ZWL 100
#define XR_PZW 103
#define XR_ZWHATL 106
#define XR_PZWHAT 156
#define XR_HL  206
#define XR_HR  462
// xtem column offsets
#define XT_G2 0
#define XT_ZW 2500
#define XT_PZW 2503
#define XT_ZWHATL 2506
#define XT_PZWHAT 2556
#define XT_HL 2606
#define XT_HR 2862

// ---------------- scratch (device globals; allocation-free) ----------------
__device__ float d_G1[(size_t)NB * LD_G1];
__device__ float d_xrel[(size_t)NB * LD_XREL];
__device__ float d_xtem[(size_t)NB * LD_XTEM];
__device__ float d_gates[(size_t)NB * 1024];
__device__ float d_hr[(size_t)NB * HID];
__device__ float d_cr[(size_t)NB * HID];
__device__ float d_Wrel[(size_t)1024 * LD_XREL];
__device__ float d_Wtem[(size_t)1024 * LD_XTEM];
__device__ float d_Wgp[(size_t)100 * LD_G1];
__device__ float d_brel[1024];
__device__ float d_btem[1024];

// ---------------- helpers ----------------
__device__ __forceinline__ float sigm(float x) { return 1.0f / (1.0f + expf(-x)); }

__device__ __forceinline__ float warp_sum(float v) {
#pragma unroll
    for (int o = 16; o; o >>= 1) v += __shfl_xor_sync(0xffffffffu, v, o);
    return v;
}

__device__ __forceinline__ float samp(const float* __restrict__ im, int y, int x) {
    if ((unsigned)y < 128u && (unsigned)x < 128u) return im[(y << 7) + x];
    return 0.0f;
}

// bilinear STN glimpse: 50x50 grid, zero padding outside, same math order as ref
__device__ __forceinline__ void do_glimpse(const float* __restrict__ imgN,
                                           float s, float tx, float ty,
                                           float* __restrict__ dst, int t) {
    for (int g = t; g < 2500; g += 256) {
        int iy = g / GNUM;
        int ix = g - iy * GNUM;
        float gx = -1.0f + (float)ix * (2.0f / 49.0f);
        float gy = -1.0f + (float)iy * (2.0f / 49.0f);
        float px = (s * gx + tx + 1.0f) * 0.5f * 127.0f;
        float py = (s * gy + ty + 1.0f) * 0.5f * 127.0f;
        float x0f = floorf(px), y0f = floorf(py);
        float wx1 = px - x0f,  wy1 = py - y0f;
        int x0 = (int)x0f, y0 = (int)y0f;
        float v00 = samp(imgN, y0,     x0);
        float v01 = samp(imgN, y0,     x0 + 1);
        float v10 = samp(imgN, y0 + 1, x0);
        float v11 = samp(imgN, y0 + 1, x0 + 1);
        float r = (1.0f - wy1) * (1.0f - wx1) * v00
                + (1.0f - wy1) * wx1          * v01
                + wy1          * (1.0f - wx1) * v10
                + wy1          * wx1          * v11;
        dst[g] = r;
    }
}

// ---------------- prep: build padded concatenated weights, zero carries ----------------
__global__ void prep_kernel(const float* __restrict__ Wih_rel, const float* __restrict__ Whh_rel,
                            const float* __restrict__ bih_rel, const float* __restrict__ bhh_rel,
                            const float* __restrict__ Wih_tem, const float* __restrict__ Whh_tem,
                            const float* __restrict__ bih_tem, const float* __restrict__ bhh_tem,
                            const float* __restrict__ Wg) {
    int tid = blockIdx.x * blockDim.x + threadIdx.x;
    int nt = gridDim.x * blockDim.x;
    for (int i = tid; i < 1024 * LD_XREL; i += nt) {
        int r = i / LD_XREL, c = i - r * LD_XREL;
        float v = 0.0f;
        if (c < 462) v = Wih_rel[r * 462 + c];
        else if (c < 718) v = Whh_rel[r * 256 + (c - 462)];
        d_Wrel[i] = v;
    }
    for (int i = tid; i < 1024 * LD_XTEM; i += nt) {
        int r = i / LD_XTEM, c = i - r * LD_XTEM;
        float v = 0.0f;
        if (c < 2862) v = Wih_tem[r * 2862 + c];
        else if (c < 3118) v = Whh_tem[r * 256 + (c - 2862)];
        d_Wtem[i] = v;
    }
    for (int i = tid; i < 100 * LD_G1; i += nt) {
        int r = i / LD_G1, c = i - r * LD_G1;
        d_Wgp[i] = (c < 2500) ? Wg[r * 2500 + c] : 0.0f;
    }
    for (int i = tid; i < 1024; i += nt) {
        d_brel[i] = bih_rel[i] + bhh_rel[i];
        d_btem[i] = bih_tem[i] + bhh_tem[i];
    }
    for (int i = tid; i < NB * HID; i += nt) {
        d_hr[i] = 0.0f;
        d_cr[i] = 0.0f;
    }
}

// ---------------- K1: zwb linear + glimpse1 + rin pack ----------------
__global__ __launch_bounds__(256) void glimpse1_kernel(
    const float* __restrict__ img, const float* __restrict__ hidden_last,
    const float* __restrict__ zwhere_last, const float* __restrict__ zwhat_last,
    const float* __restrict__ W_loca, const float* __restrict__ b_loca,
    const float* __restrict__ zwhere_out, const float* __restrict__ zwhat_out, int k) {
    int n = blockIdx.x, t = threadIdx.x;
    __shared__ float sred[3][8];
    __shared__ float szw[3];
    int w = t >> 5, lane = t & 31;

    float h = hidden_last[((size_t)n * KS + k) * HID + t];
    float p0 = h * W_loca[t];
    float p1 = h * W_loca[HID + t];
    float p2 = h * W_loca[2 * HID + t];
    p0 = warp_sum(p0); p1 = warp_sum(p1); p2 = warp_sum(p2);
    if (lane == 0) { sred[0][w] = p0; sred[1][w] = p1; sred[2][w] = p2; }

    float* xr = d_xrel + (size_t)n * LD_XREL;
    xr[XR_HL + t] = h;
    xr[XR_HR + t] = d_hr[n * HID + t];
    if (t < 3) {
        xr[XR_ZWL + t] = zwhere_last[((size_t)n * KS + k) * 3 + t];
        xr[XR_PZW + t] = k ? zwhere_out[((size_t)n * KS + k - 1) * 3 + t] : 0.0f;
    }
    if (t < 50) {
        xr[XR_ZWHATL + t] = zwhat_last[((size_t)n * KS + k) * 50 + t];
        xr[XR_PZWHAT + t] = k ? zwhat_out[((size_t)n * KS + k - 1) * 50 + t] : 0.0f;
    }
    __syncthreads();
    if (t < 3) {
        float s = 0.0f;
#pragma unroll
        for (int q = 0; q < 8; q++) s += sred[t][q];
        s += b_loca[t];
        s = fmaxf(s, 0.0f) + zwhere_last[((size_t)n * KS + k) * 3 + t];
        szw[t] = s;
    }
    __syncthreads();
    do_glimpse(img + (size_t)n * IMG_HW, szw[0], szw[1], szw[2], d_G1 + (size_t)n * LD_G1, t);
}

// ---------------- generic fp32 tiled GEMM: C = act(A * B^T + bias) ----------------
// A[M,K] lda, B[N,K] ldb (weight layout), C[M,N] ldc. K % BK == 0, M % BM == 0.
template <int BM, int BN, int BK, int TM, int TN, int ACT>
__global__ __launch_bounds__(256, 2) void gemm_kernel(
    const float* __restrict__ A, int lda,
    const float* __restrict__ B, int ldb,
    const float* __restrict__ bias,
    float* __restrict__ C, int ldc, int N, int K) {
    __shared__ float As[BK][BM + 1];
    __shared__ float Bs[BK][BN + 1];
    const int tid = threadIdx.x;
    const int bm = blockIdx.y * BM;
    const int bn = blockIdx.x * BN;
    const int TCOLS = BN / TN;
    const int tm = (tid / TCOLS) * TM;
    const int tn = (tid % TCOLS) * TN;
    float acc[TM][TN];
#pragma unroll
    for (int i = 0; i < TM; i++)
#pragma unroll
        for (int j = 0; j < TN; j++) acc[i][j] = 0.0f;

    constexpr int APT = BM * BK / 256;
    constexpr int BPT = BN * BK / 256;
    for (int k0 = 0; k0 < K; k0 += BK) {
#pragma unroll
        for (int i = 0; i < APT; i++) {
            int e = tid + 256 * i;
            int kk = e % BK, mm = e / BK;
            As[kk][mm] = A[(size_t)(bm + mm) * lda + k0 + kk];
        }
#pragma unroll
        for (int i = 0; i < BPT; i++) {
            int e = tid + 256 * i;
            int kk = e % BK, nn = e / BK;
            int gn = bn + nn;
            Bs[kk][nn] = (gn < N) ? B[(size_t)gn * ldb + k0 + kk] : 0.0f;
        }
        __syncthreads();
#pragma unroll
        for (int kk = 0; kk < BK; kk++) {
            float a[TM], b[TN];
#pragma unroll
            for (int i = 0; i < TM; i++) a[i] = As[kk][tm + i];
#pragma unroll
            for (int j = 0; j < TN; j++) b[j] = Bs[kk][tn + j];
#pragma unroll
            for (int i = 0; i < TM; i++)
#pragma unroll
                for (int j = 0; j < TN; j++) acc[i][j] = fmaf(a[i], b[j], acc[i][j]);
        }
        __syncthreads();
    }
#pragma unroll
    for (int j = 0; j < TN; j++) {
        int gn = bn + tn + j;
        if (gn < N) {
            float bv = bias[gn];
#pragma unroll
            for (int i = 0; i < TM; i++) {
                float v = acc[i][j] + bv;
                if (ACT) v = fmaxf(v, 0.0f);
                C[(size_t)(bm + tm + i) * ldc + gn] = v;
            }
        }
    }
}

// ---------------- K4: rel LSTM pointwise + zw linear + glimpse2 + tin pack ----------------
__global__ __launch_bounds__(256) void relglimpse2_kernel(
    const float* __restrict__ img, const float* __restrict__ hidden_last,
    const float* __restrict__ zwhere_last, const float* __restrict__ zwhat_last,
    const float* __restrict__ Wm_wh, const float* __restrict__ bm_wh,
    const float* __restrict__ zwhat_out, float* __restrict__ zwhere_out, int k) {
    int n = blockIdx.x, t = threadIdx.x;
    __shared__ float hs[HID];
    __shared__ float sred[3][8];
    __shared__ float szw[3];
    int w = t >> 5, lane = t & 31;

    const float* g = d_gates + (size_t)n * 1024;
    float iv = sigm(g[t]);
    float fv = sigm(g[256 + t]);
    float gv = tanhf(g[512 + t]);
    float ov = sigm(g[768 + t]);
    float c2 = fv * d_cr[n * HID + t] + iv * gv;
    float h = ov * tanhf(c2);
    d_cr[n * HID + t] = c2;
    d_hr[n * HID + t] = h;
    hs[t] = h;

    float* xt = d_xtem + (size_t)n * LD_XTEM;
    xt[XT_HR + t] = h;
    xt[XT_HL + t] = hidden_last[((size_t)n * KS + k) * HID + t];
    if (t < 3) xt[XT_PZW + t] = k ? zwhere_out[((size_t)n * KS + k - 1) * 3 + t] : 0.0f;
    if (t < 50) {
        xt[XT_ZWHATL + t] = zwhat_last[((size_t)n * KS + k) * 50 + t];
        xt[XT_PZWHAT + t] = k ? zwhat_out[((size_t)n * KS + k - 1) * 50 + t] : 0.0f;
    }
    __syncthreads();

    // zw = [zwl(3), h_r2(256)] @ Wm_wh^T + bm_wh  (K=259)
    float c0 = (t < 3) ? zwhere_last[((size_t)n * KS + k) * 3 + t] : hs[t - 3];
    float q0 = c0 * Wm_wh[t];
    float q1 = c0 * Wm_wh[259 + t];
    float q2 = c0 * Wm_wh[518 + t];
    if (t < 3) {
        float c1 = hs[253 + t];
        q0 += c1 * Wm_wh[256 + t];
        q1 += c1 * Wm_wh[259 + 256 + t];
        q2 += c1 * Wm_wh[518 + 256 + t];
    }
    q0 = warp_sum(q0); q1 = warp_sum(q1); q2 = warp_sum(q2);
    if (lane == 0) { sred[0][w] = q0; sred[1][w] = q1; sred[2][w] = q2; }
    __syncthreads();
    if (t < 3) {
        float s = 0.0f;
#pragma unroll
        for (int q = 0; q < 8; q++) s += sred[t][q];
        s += bm_wh[t];
        szw[t] = s;
        zwhere_out[((size_t)n * KS + k) * 3 + t] = s;
        xt[XT_ZW + t] = s;
    }
    __syncthreads();
    do_glimpse(img + (size_t)n * IMG_HW, szw[0], szw[1], szw[2], xt, t);
}

// ---------------- K6: tem LSTM pointwise + zwhat GEMV + presence head ----------------
__global__ __launch_bounds__(256) void head_kernel(
    const float* __restrict__ zwhat_last, const float* __restrict__ zpres_last,
    const float* __restrict__ Wm_wt, const float* __restrict__ bm_wt,
    const float* __restrict__ Wm_pr, const float* __restrict__ bm_pr,
    const float* __restrict__ Ws_pr, const float* __restrict__ bs_pr,
    const float* __restrict__ zwhere_out, float* __restrict__ zwhat_out,
    float* __restrict__ zpres_out, float* __restrict__ htemp_out, int k) {
    int n = blockIdx.x, t = threadIdx.x;
    __shared__ float xs[562];  // [zwhatl(50) | h_r2(256) | h_t(256)]
    __shared__ float ys[565];  // [zwhat(50) | zw(3) | h_r2(256) | h_t(256)]
    __shared__ float red[16];
    int w = t >> 5, lane = t & 31;

    const float* g = d_gates + (size_t)n * 1024;
    float iv = sigm(g[t]);
    float fv = sigm(g[256 + t]);
    float gv = tanhf(g[512 + t]);
    float ov = sigm(g[768 + t]);
    float c2 = fv * d_cr[n * HID + t] + iv * gv;  // c_r holds c_r2 (do not overwrite)
    float ht = ov * tanhf(c2);
    htemp_out[((size_t)n * KS + k) * HID + t] = ht;

    float hr = d_hr[n * HID + t];
    xs[50 + t] = hr; xs[306 + t] = ht;
    ys[53 + t] = hr; ys[309 + t] = ht;
    if (t < 50) xs[t] = zwhat_last[((size_t)n * KS + k) * 50 + t];
    if (t < 3) ys[50 + t] = zwhere_out[((size_t)n * KS + k) * 3 + t];
    __syncthreads();

    // zwhat: 50 outputs, one per warp round-robin; K = 562
    for (int j = w; j < 50; j += 8) {
        const float* wr = Wm_wt + (size_t)j * 562;
        float acc = 0.0f;
        for (int i = lane; i < 562; i += 32) acc += xs[i] * wr[i];
        acc = warp_sum(acc);
        if (lane == 0) {
            float z = acc + bm_wt[j];
            ys[j] = z;
            zwhat_out[((size_t)n * KS + k) * 50 + j] = z;
        }
    }
    __syncthreads();

    // presence: two 565-dots across the block
    float am = 0.0f, as = 0.0f;
    for (int i = t; i < 565; i += 256) {
        float x = ys[i];
        am += x * Wm_pr[i];
        as += x * Ws_pr[i];
    }
    am = warp_sum(am); as = warp_sum(as);
    if (lane == 0) { red[w] = am; red[8 + w] = as; }
    __syncthreads();
    if (t == 0) {
        float m = 0.0f, s = 0.0f;
#pragma unroll
        for (int q = 0; q < 8; q++) { m += red[q]; s += red[8 + q]; }
        float p = sigm(m + bm_pr[0]) * sigm(s + bs_pr[0]);
        zpres_out[(size_t)n * KS + k] = p * zpres_last[(size_t)n * KS + k];
    }
}

// ---------------- host ----------------
extern "C" void kernel_launch(void* const* d_in, const int* in_sizes, int n_in,
                              void* d_out, int out_size) {
    const float* img         = (const float*)d_in[0];
    const float* zwhat_last  = (const float*)d_in[1];
    const float* zwhere_last = (const float*)d_in[2];
    const float* zpres_last  = (const float*)d_in[3];
    const float* hidden_last = (const float*)d_in[4];
    const float* W_loca = (const float*)d_in[5];
    const float* b_loca = (const float*)d_in[6];
    const float* Wg     = (const float*)d_in[7];
    const float* bg     = (const float*)d_in[8];
    const float* Wih_rel = (const float*)d_in[9];
    const float* Whh_rel = (const float*)d_in[10];
    const float* bih_rel = (const float*)d_in[11];
    const float* bhh_rel = (const float*)d_in[12];
    const float* Wih_tem = (const float*)d_in[13];
    const float* Whh_tem = (const float*)d_in[14];
    const float* bih_tem = (const float*)d_in[15];
    const float* bhh_tem = (const float*)d_in[16];
    const float* Wm_wh = (const float*)d_in[17];
    const float* bm_wh = (const float*)d_in[18];
    // d_in[19], d_in[20] = Ws_wh, bs_wh (unused by reference)
    const float* Wm_wt = (const float*)d_in[21];
    const float* bm_wt = (const float*)d_in[22];
    // d_in[23], d_in[24] = Ws_wt, bs_wt (unused by reference)
    const float* Wm_pr = (const float*)d_in[25];
    const float* bm_pr = (const float*)d_in[26];
    const float* Ws_pr = (const float*)d_in[27];
    const float* bs_pr = (const float*)d_in[28];

    float* out = (float*)d_out;
    // outputs concatenated in return order
    float* zwhat_out  = out;                                   // [N,K,50]
    float* zwhere_out = out + (size_t)NB * KS * 50;            // [N,K,3]
    float* zpres_out  = zwhere_out + (size_t)NB * KS * 3;      // [N,K,1]
    float* htemp_out  = zpres_out + (size_t)NB * KS * 1;       // [N,K,256]

    void *pG1, *pXrel, *pXtem, *pGates, *pWrel, *pWtem, *pWgp, *pBrel, *pBtem;
    cudaGetSymbolAddress(&pG1, d_G1);
    cudaGetSymbolAddress(&pXrel, d_xrel);
    cudaGetSymbolAddress(&pXtem, d_xtem);
    cudaGetSymbolAddress(&pGates, d_gates);
    cudaGetSymbolAddress(&pWrel, d_Wrel);
    cudaGetSymbolAddress(&pWtem, d_Wtem);
    cudaGetSymbolAddress(&pWgp, d_Wgp);
    cudaGetSymbolAddress(&pBrel, d_brel);
    cudaGetSymbolAddress(&pBtem, d_btem);

    prep_kernel<<<2048, 256>>>(Wih_rel, Whh_rel, bih_rel, bhh_rel,
                               Wih_tem, Whh_tem, bih_tem, bhh_tem, Wg);

    for (int k = 0; k < KS; k++) {
        glimpse1_kernel<<<NB, 256>>>(img, hidden_last, zwhere_last, zwhat_last,
                                     W_loca, b_loca, zwhere_out, zwhat_out, k);

        // enc = relu(G1 @ Wg^T + bg) -> xrel[:, 0:100]   (M=2048, N=100, K=2512)
        {
            dim3 grid((100 + 31) / 32, NB / 64);
            gemm_kernel<64, 32, 16, 4, 2, 1><<<grid, 256>>>(
                (const float*)pG1, LD_G1, (const float*)pWgp, LD_G1, bg,
                (float*)pXrel, LD_XREL, 100, LD_G1);
        }
        // rel gates = xrel @ [Wih_rel|Whh_rel]^T + (bih+bhh)   (M=2048, N=1024, K=720)
        {
            dim3 grid(1024 / 64, NB / 128);
            gemm_kernel<128, 64, 16, 8, 4, 0><<<grid, 256>>>(
                (const float*)pXrel, LD_XREL, (const float*)pWrel, LD_XREL,
                (const float*)pBrel, (float*)pGates, 1024, 1024, LD_XREL);
        }
        relglimpse2_kernel<<<NB, 256>>>(img, hidden_last, zwhere_last, zwhat_last,
                                        Wm_wh, bm_wh, zwhat_out, zwhere_out, k);
        // tem gates = xtem @ [Wih_tem|Whh_tem]^T + (bih+bhh)   (M=2048, N=1024, K=3120)
        {
            dim3 grid(1024 / 64, NB / 128);
            gemm_kernel<128, 64, 16, 8, 4, 0><<<grid, 256>>>(
                (const float*)pXtem, LD_XTEM, (const float*)pWtem, LD_XTEM,
                (const float*)pBtem, (float*)pGates, 1024, 1024, LD_XTEM);
        }
        head_kernel<<<NB, 256>>>(zwhat_last, zpres_last, Wm_wt, bm_wt,
                                 Wm_pr, bm_pr, Ws_pr, bs_pr,
                                 zwhere_out, zwhat_out, zpres_out, htemp_out, k);
    }
}

// round 5
// speedup vs baseline: 2.7066x; 2.7066x over previous
#include <cuda_runtime.h>
#include <cuda_bf16.h>
#include <cstdint>
#include <math.h>

#define NB   2048
#define KS   8
#define HID  256
#define IMG_HW 16384

#define KENC 2560   // glimpse K padded (2500 real)
#define KREL 768    // rel K padded (718 real)
#define KTEM 3136   // tem K padded (3118 real)
#define NGATE 1024

// xrel col offsets: [enc100|zwl3|pzw3|zwhatl50|pzwhat50|hl256|h_r256]
#define XR_ZWL 100
#define XR_PZW 103
#define XR_ZWHATL 106
#define XR_PZWHAT 156
#define XR_HL  206
#define XR_HR  462
// xtem col offsets: [g2 2500|zw3|pzw3|zwhatl50|pzwhat50|hl256|h_r2 256]
#define XT_ZW 2500
#define XT_PZW 2503
#define XT_ZWHATL 2506
#define XT_PZWHAT 2556
#define XT_HL 2606
#define XT_HR 2862

// ---------------- scratch ----------------
__device__ __nv_bfloat16 d_G1h[(size_t)NB * KS * KENC];
__device__ __nv_bfloat16 d_G1l[(size_t)NB * KS * KENC];
__device__ __nv_bfloat16 d_xrh[(size_t)NB * KS * KREL];
__device__ __nv_bfloat16 d_xrl[(size_t)NB * KS * KREL];
__device__ __nv_bfloat16 d_xth[(size_t)NB * KTEM];
__device__ __nv_bfloat16 d_xtl[(size_t)NB * KTEM];
__device__ float d_gates[(size_t)NB * NGATE];
__device__ float d_hr[(size_t)NB * HID];
__device__ float d_cr[(size_t)NB * HID];
__device__ __nv_bfloat16 d_Wrh[(size_t)NGATE * KREL];
__device__ __nv_bfloat16 d_Wrl[(size_t)NGATE * KREL];
__device__ __nv_bfloat16 d_Wth[(size_t)NGATE * KTEM];
__device__ __nv_bfloat16 d_Wtl[(size_t)NGATE * KTEM];
__device__ __nv_bfloat16 d_Wgh[(size_t)128 * KENC];
__device__ __nv_bfloat16 d_Wgl[(size_t)128 * KENC];
__device__ float d_brel[NGATE];
__device__ float d_btem[NGATE];

// ---------------- ptx helpers (all sm_80-era, safe for compute_103 PTX) ----------------
__device__ __forceinline__ uint32_t smem_u32(const void* p) {
    uint32_t a;
    asm("{ .reg .u64 t; cvta.to.shared.u64 t, %1; cvt.u32.u64 %0, t; }" : "=r"(a) : "l"(p));
    return a;
}
__device__ __forceinline__ void cp16(uint32_t dst, const void* src) {
    asm volatile("cp.async.ca.shared.global [%0], [%1], 16;" :: "r"(dst), "l"(src));
}
__device__ __forceinline__ void cp_commit() { asm volatile("cp.async.commit_group;"); }
__device__ __forceinline__ void cp_wait1() { asm volatile("cp.async.wait_group 1;"); }
__device__ __forceinline__ void cp_wait0() { asm volatile("cp.async.wait_group 0;"); }
__device__ __forceinline__ void ldm_x4(uint32_t* r, uint32_t a) {
    asm volatile("ldmatrix.sync.aligned.m8n8.x4.shared.b16 {%0,%1,%2,%3}, [%4];"
                 : "=r"(r[0]), "=r"(r[1]), "=r"(r[2]), "=r"(r[3]) : "r"(a));
}
__device__ __forceinline__ void ldm_x2(uint32_t* r, uint32_t a) {
    asm volatile("ldmatrix.sync.aligned.m8n8.x2.shared.b16 {%0,%1}, [%2];"
                 : "=r"(r[0]), "=r"(r[1]) : "r"(a));
}
__device__ __forceinline__ void mma_bf16(float* c, const uint32_t* a, const uint32_t* b) {
    asm volatile("mma.sync.aligned.m16n8k16.row.col.f32.bf16.bf16.f32 "
                 "{%0,%1,%2,%3}, {%4,%5,%6,%7}, {%8,%9}, {%0,%1,%2,%3};"
                 : "+f"(c[0]), "+f"(c[1]), "+f"(c[2]), "+f"(c[3])
                 : "r"(a[0]), "r"(a[1]), "r"(a[2]), "r"(a[3]), "r"(b[0]), "r"(b[1]));
}

// ---------------- math helpers ----------------
__device__ __forceinline__ float sigm(float x) { return 1.0f / (1.0f + expf(-x)); }
__device__ __forceinline__ float warp_sum(float v) {
#pragma unroll
    for (int o = 16; o; o >>= 1) v += __shfl_xor_sync(0xffffffffu, v, o);
    return v;
}
__device__ __forceinline__ void wpair(__nv_bfloat16* ph, __nv_bfloat16* pl, int i, float x) {
    __nv_bfloat16 h = __float2bfloat16(x);
    ph[i] = h;
    pl[i] = __float2bfloat16(x - __bfloat162float(h));
}
__device__ __forceinline__ float samp(const float* __restrict__ im, int y, int x) {
    if ((unsigned)y < 128u && (unsigned)x < 128u) return im[(y << 7) + x];
    return 0.0f;
}
__device__ __forceinline__ void glimpse_pair(const float* __restrict__ imgN,
                                             float s, float tx, float ty,
                                             __nv_bfloat16* __restrict__ dh,
                                             __nv_bfloat16* __restrict__ dl, int t) {
    for (int g = t; g < 2500; g += 256) {
        int iy = g / 50, ix = g - iy * 50;
        float gx = -1.0f + (float)ix * (2.0f / 49.0f);
        float gy = -1.0f + (float)iy * (2.0f / 49.0f);
        float px = (s * gx + tx + 1.0f) * 0.5f * 127.0f;
        float py = (s * gy + ty + 1.0f) * 0.5f * 127.0f;
        float x0f = floorf(px), y0f = floorf(py);
        float wx1 = px - x0f, wy1 = py - y0f;
        int x0 = (int)x0f, y0 = (int)y0f;
        float v00 = samp(imgN, y0, x0),     v01 = samp(imgN, y0, x0 + 1);
        float v10 = samp(imgN, y0 + 1, x0), v11 = samp(imgN, y0 + 1, x0 + 1);
        float r = (1.0f - wy1) * (1.0f - wx1) * v00 + (1.0f - wy1) * wx1 * v01
                + wy1 * (1.0f - wx1) * v10 + wy1 * wx1 * v11;
        wpair(dh, dl, g, r);
    }
}

// ---------------- prep ----------------
__global__ void prep_kernel(const float* __restrict__ Wih_rel, const float* __restrict__ Whh_rel,
                            const float* __restrict__ bih_rel, const float* __restrict__ bhh_rel,
                            const float* __restrict__ Wih_tem, const float* __restrict__ Whh_tem,
                            const float* __restrict__ bih_tem, const float* __restrict__ bhh_tem,
                            const float* __restrict__ Wg) {
    int tid = blockIdx.x * blockDim.x + threadIdx.x;
    int nt = gridDim.x * blockDim.x;
    for (int i = tid; i < NGATE * KREL; i += nt) {
        int r = i / KREL, c = i - r * KREL;
        float v = 0.0f;
        if (c < 462) v = Wih_rel[r * 462 + c];
        else if (c < 718) v = Whh_rel[r * 256 + (c - 462)];
        wpair(d_Wrh, d_Wrl, i, v);
    }
    for (int i = tid; i < NGATE * KTEM; i += nt) {
        int r = i / KTEM, c = i - r * KTEM;
        float v = 0.0f;
        if (c < 2862) v = Wih_tem[r * 2862 + c];
        else if (c < 3118) v = Whh_tem[r * 256 + (c - 2862)];
        wpair(d_Wth, d_Wtl, i, v);
    }
    for (int i = tid; i < 128 * KENC; i += nt) {
        int r = i / KENC, c = i - r * KENC;
        float v = (r < 100 && c < 2500) ? Wg[r * 2500 + c] : 0.0f;
        wpair(d_Wgh, d_Wgl, i, v);
    }
    for (int i = tid; i < NGATE; i += nt) {
        d_brel[i] = bih_rel[i] + bhh_rel[i];
        d_btem[i] = bih_tem[i] + bhh_tem[i];
    }
    for (int i = tid; i < NB * HID; i += nt) { d_hr[i] = 0.0f; d_cr[i] = 0.0f; }
    // pads
    for (int i = tid; i < NB * KS * 60; i += nt) {
        int r = i / 60, c = 2500 + i % 60;
        d_G1h[(size_t)r * KENC + c] = __float2bfloat16(0.0f);
        d_G1l[(size_t)r * KENC + c] = __float2bfloat16(0.0f);
    }
    for (int i = tid; i < NB * KS * 50; i += nt) {
        int r = i / 50, c = 718 + i % 50;
        d_xrh[(size_t)r * KREL + c] = __float2bfloat16(0.0f);
        d_xrl[(size_t)r * KREL + c] = __float2bfloat16(0.0f);
    }
    for (int i = tid; i < NB * 18; i += nt) {
        int r = i / 18, c = 3118 + i % 18;
        d_xth[(size_t)r * KTEM + c] = __float2bfloat16(0.0f);
        d_xtl[(size_t)r * KTEM + c] = __float2bfloat16(0.0f);
    }
}

// ---------------- static pack: zwb + glimpse1 + static xrel cols, all (n,k) ----------------
__global__ __launch_bounds__(256) void staticpack_kernel(
    const float* __restrict__ img, const float* __restrict__ hidden_last,
    const float* __restrict__ zwhere_last, const float* __restrict__ zwhat_last,
    const float* __restrict__ W_loca, const float* __restrict__ b_loca) {
    int b = blockIdx.x, t = threadIdx.x;   // b = n*8 + k
    int n = b >> 3;
    __shared__ float sred[3][8];
    __shared__ float szw[3];
    int w = t >> 5, lane = t & 31;

    float h = hidden_last[(size_t)b * HID + t];
    float p0 = h * W_loca[t];
    float p1 = h * W_loca[HID + t];
    float p2 = h * W_loca[2 * HID + t];
    p0 = warp_sum(p0); p1 = warp_sum(p1); p2 = warp_sum(p2);
    if (lane == 0) { sred[0][w] = p0; sred[1][w] = p1; sred[2][w] = p2; }

    __nv_bfloat16* xh = d_xrh + (size_t)b * KREL;
    __nv_bfloat16* xl = d_xrl + (size_t)b * KREL;
    wpair(xh, xl, XR_HL + t, h);
    if (t < 3)  wpair(xh, xl, XR_ZWL + t, zwhere_last[(size_t)b * 3 + t]);
    if (t < 50) wpair(xh, xl, XR_ZWHATL + t, zwhat_last[(size_t)b * 50 + t]);
    __syncthreads();
    if (t < 3) {
        float s = 0.0f;
#pragma unroll
        for (int q = 0; q < 8; q++) s += sred[t][q];
        s += b_loca[t];
        szw[t] = fmaxf(s, 0.0f) + zwhere_last[(size_t)b * 3 + t];
    }
    __syncthreads();
    glimpse_pair(img + (size_t)n * IMG_HW, szw[0], szw[1], szw[2],
                 d_G1h + (size_t)b * KENC, d_G1l + (size_t)b * KENC, t);
}

// ---------------- recpack: recurrent xrel cols for step k ----------------
__global__ __launch_bounds__(256) void recpack_kernel(
    const float* __restrict__ zwhere_out, const float* __restrict__ zwhat_out, int k) {
    int n = blockIdx.x, t = threadIdx.x;
    size_t row = (size_t)n * KS + k;
    __nv_bfloat16* xh = d_xrh + row * KREL;
    __nv_bfloat16* xl = d_xrl + row * KREL;
    wpair(xh, xl, XR_HR + t, d_hr[n * HID + t]);
    if (t < 3)  wpair(xh, xl, XR_PZW + t, k ? zwhere_out[((size_t)n * KS + k - 1) * 3 + t] : 0.0f);
    if (t < 50) wpair(xh, xl, XR_PZWHAT + t, k ? zwhat_out[((size_t)n * KS + k - 1) * 50 + t] : 0.0f);
}

// ---------------- HMMA split-bf16 GEMM: C = A*B^T + bias ----------------
// CTA 128x128, BK=32. smem rows stride 80B (5x16B chunks, gcd(5,8)=1 -> ldmatrix conflict-free).
#define TILE_B 10240                 // 128 rows * 80 B
#define STAGE_B (4 * TILE_B)         // Ah, Al, Bh, Bl
#define SMEM_REQ (2 * STAGE_B)       // 81920

template <int EPI>   // 0: f32 out (gates), 1: relu -> (hi,lo) bf16 out
__global__ __launch_bounds__(256) void hmma_gemm(
    const __nv_bfloat16* __restrict__ Ah, const __nv_bfloat16* __restrict__ Al, int lda,
    const __nv_bfloat16* __restrict__ Bh, const __nv_bfloat16* __restrict__ Bl, int ldb,
    const float* __restrict__ bias,
    float* __restrict__ Cf, __nv_bfloat16* __restrict__ Chi,
    __nv_bfloat16* __restrict__ Clo, int ldc, int K, int nReal) {
    extern __shared__ char smem[];
    const uint32_t sb = smem_u32(smem);
    const int tid = threadIdx.x;
    const int lane = tid & 31, wid = tid >> 5;
    const int wm = wid >> 2, wn = wid & 3;      // 2 x 4 warp grid
    const int bm = blockIdx.y * 128, bn = blockIdx.x * 128;
    const int nK = K / 32;

    float acc[4][4][4];
#pragma unroll
    for (int i = 0; i < 4; i++)
#pragma unroll
        for (int j = 0; j < 4; j++)
#pragma unroll
            for (int q = 0; q < 4; q++) acc[i][j][q] = 0.0f;

    auto load_stage = [&](int st, int kt) {
        int k0 = kt * 32;
        uint32_t base = sb + st * STAGE_B;
#pragma unroll
        for (int q = 0; q < 8; q++) {
            int idx = q * 256 + tid;         // 0..2047
            int tile = idx >> 9;
            int rem = idx & 511;
            int row = rem >> 2;
            int ch = rem & 3;
            const __nv_bfloat16* gp;
            if (tile == 0)      gp = Ah + (size_t)(bm + row) * lda + k0 + ch * 8;
            else if (tile == 1) gp = Al + (size_t)(bm + row) * lda + k0 + ch * 8;
            else if (tile == 2) gp = Bh + (size_t)(bn + row) * ldb + k0 + ch * 8;
            else                gp = Bl + (size_t)(bn + row) * ldb + k0 + ch * 8;
            cp16(base + tile * TILE_B + row * 80 + ch * 16, gp);
        }
        cp_commit();
    };

    load_stage(0, 0);
    for (int kt = 0; kt < nK; kt++) {
        if (kt + 1 < nK) { load_stage((kt + 1) & 1, kt + 1); cp_wait1(); }
        else cp_wait0();
        __syncthreads();
        uint32_t base = sb + (kt & 1) * STAGE_B;
#pragma unroll
        for (int ks = 0; ks < 2; ks++) {
            uint32_t ah[4][4], al[4][4], bh[4][2], bl[4][2];
#pragma unroll
            for (int mf = 0; mf < 4; mf++) {
                int row = wm * 64 + mf * 16 + (lane & 15);
                int ch = ks * 2 + (lane >> 4);
                uint32_t a = base + row * 80 + ch * 16;
                ldm_x4(ah[mf], a);
                ldm_x4(al[mf], a + TILE_B);
            }
#pragma unroll
            for (int nf = 0; nf < 4; nf++) {
                int row = wn * 32 + nf * 8 + (lane & 7);
                int ch = ks * 2 + ((lane >> 3) & 1);
                uint32_t a = base + 2 * TILE_B + row * 80 + ch * 16;
                ldm_x2(bh[nf], a);
                ldm_x2(bl[nf], a + TILE_B);
            }
#pragma unroll
            for (int mf = 0; mf < 4; mf++)
#pragma unroll
                for (int nf = 0; nf < 4; nf++) {
                    mma_bf16(acc[mf][nf], ah[mf], bh[nf]);
                    mma_bf16(acc[mf][nf], al[mf], bh[nf]);
                    mma_bf16(acc[mf][nf], ah[mf], bl[nf]);
                }
        }
        __syncthreads();
    }

    // epilogue
    int trow = lane >> 2, tcol = (lane & 3) * 2;
#pragma unroll
    for (int mf = 0; mf < 4; mf++) {
        int r0 = bm + wm * 64 + mf * 16 + trow;
#pragma unroll
        for (int nf = 0; nf < 4; nf++) {
            int col = bn + wn * 32 + nf * 8 + tcol;
            if (EPI == 0) {
                float b0 = bias[col], b1 = bias[col + 1];
                Cf[(size_t)r0 * ldc + col]           = acc[mf][nf][0] + b0;
                Cf[(size_t)r0 * ldc + col + 1]       = acc[mf][nf][1] + b1;
                Cf[(size_t)(r0 + 8) * ldc + col]     = acc[mf][nf][2] + b0;
                Cf[(size_t)(r0 + 8) * ldc + col + 1] = acc[mf][nf][3] + b1;
            } else {
#pragma unroll
                for (int e = 0; e < 4; e++) {
                    int cc = col + (e & 1);
                    int rr = r0 + (e >> 1) * 8;
                    if (cc < nReal) {
                        float v = fmaxf(acc[mf][nf][e] + bias[cc], 0.0f);
                        wpair(Chi + (size_t)rr * ldc, Clo + (size_t)rr * ldc, cc, v);
                    }
                }
            }
        }
    }
}

// ---------------- rel LSTM + zw + glimpse2 + xtem pack ----------------
__global__ __launch_bounds__(256) void relglimpse2_kernel(
    const float* __restrict__ img, const float* __restrict__ hidden_last,
    const float* __restrict__ zwhere_last, const float* __restrict__ zwhat_last,
    const float* __restrict__ Wm_wh, const float* __restrict__ bm_wh,
    const float* __restrict__ zwhat_out, float* __restrict__ zwhere_out, int k) {
    int n = blockIdx.x, t = threadIdx.x;
    __shared__ float hs[HID];
    __shared__ float sred[3][8];
    __shared__ float szw[3];
    int w = t >> 5, lane = t & 31;

    const float* g = d_gates + (size_t)n * NGATE;
    float iv = sigm(g[t]);
    float fv = sigm(g[256 + t]);
    float gv = tanhf(g[512 + t]);
    float ov = sigm(g[768 + t]);
    float c2 = fv * d_cr[n * HID + t] + iv * gv;
    float h = ov * tanhf(c2);
    d_cr[n * HID + t] = c2;
    d_hr[n * HID + t] = h;
    hs[t] = h;

    __nv_bfloat16* xh = d_xth + (size_t)n * KTEM;
    __nv_bfloat16* xl = d_xtl + (size_t)n * KTEM;
    wpair(xh, xl, XT_HR + t, h);
    wpair(xh, xl, XT_HL + t, hidden_last[((size_t)n * KS + k) * HID + t]);
    if (t < 3) wpair(xh, xl, XT_PZW + t, k ? zwhere_out[((size_t)n * KS + k - 1) * 3 + t] : 0.0f);
    if (t < 50) {
        wpair(xh, xl, XT_ZWHATL + t, zwhat_last[((size_t)n * KS + k) * 50 + t]);
        wpair(xh, xl, XT_PZWHAT + t, k ? zwhat_out[((size_t)n * KS + k - 1) * 50 + t] : 0.0f);
    }
    __syncthreads();

    // zw = [zwl(3), h_r2(256)] @ Wm_wh^T + bm_wh (K=259)
    float c0 = (t < 3) ? zwhere_last[((size_t)n * KS + k) * 3 + t] : hs[t - 3];
    float q0 = c0 * Wm_wh[t];
    float q1 = c0 * Wm_wh[259 + t];
    float q2 = c0 * Wm_wh[518 + t];
    if (t < 3) {
        float c1 = hs[253 + t];
        q0 += c1 * Wm_wh[256 + t];
        q1 += c1 * Wm_wh[259 + 256 + t];
        q2 += c1 * Wm_wh[518 + 256 + t];
    }
    q0 = warp_sum(q0); q1 = warp_sum(q1); q2 = warp_sum(q2);
    if (lane == 0) { sred[0][w] = q0; sred[1][w] = q1; sred[2][w] = q2; }
    __syncthreads();
    if (t < 3) {
        float s = 0.0f;
#pragma unroll
        for (int q = 0; q < 8; q++) s += sred[t][q];
        s += bm_wh[t];
        szw[t] = s;
        zwhere_out[((size_t)n * KS + k) * 3 + t] = s;
        wpair(xh, xl, XT_ZW + t, s);
    }
    __syncthreads();
    glimpse_pair(img + (size_t)n * IMG_HW, szw[0], szw[1], szw[2], xh, xl, t);
}

// ---------------- tem LSTM + zwhat + presence ----------------
__global__ __launch_bounds__(256) void head_kernel(
    const float* __restrict__ zwhat_last, const float* __restrict__ zpres_last,
    const float* __restrict__ Wm_wt, const float* __restrict__ bm_wt,
    const float* __restrict__ Wm_pr, const float* __restrict__ bm_pr,
    const float* __restrict__ Ws_pr, const float* __restrict__ bs_pr,
    const float* __restrict__ zwhere_out, float* __restrict__ zwhat_out,
    float* __restrict__ zpres_out, float* __restrict__ htemp_out, int k) {
    int n = blockIdx.x, t = threadIdx.x;
    __shared__ float xs[562];
    __shared__ float ys[565];
    __shared__ float red[16];
    int w = t >> 5, lane = t & 31;

    const float* g = d_gates + (size_t)n * NGATE;
    float iv = sigm(g[t]);
    float fv = sigm(g[256 + t]);
    float gv = tanhf(g[512 + t]);
    float ov = sigm(g[768 + t]);
    float c2 = fv * d_cr[n * HID + t] + iv * gv;
    float ht = ov * tanhf(c2);
    htemp_out[((size_t)n * KS + k) * HID + t] = ht;

    float hr = d_hr[n * HID + t];
    xs[50 + t] = hr; xs[306 + t] = ht;
    ys[53 + t] = hr; ys[309 + t] = ht;
    if (t < 50) xs[t] = zwhat_last[((size_t)n * KS + k) * 50 + t];
    if (t < 3) ys[50 + t] = zwhere_out[((size_t)n * KS + k) * 3 + t];
    __syncthreads();

    for (int j = w; j < 50; j += 8) {
        const float* wr = Wm_wt + (size_t)j * 562;
        float acc = 0.0f;
        for (int i = lane; i < 562; i += 32) acc += xs[i] * wr[i];
        acc = warp_sum(acc);
        if (lane == 0) {
            float z = acc + bm_wt[j];
            ys[j] = z;
            zwhat_out[((size_t)n * KS + k) * 50 + j] = z;
        }
    }
    __syncthreads();

    float am = 0.0f, as = 0.0f;
    for (int i = t; i < 565; i += 256) {
        float x = ys[i];
        am += x * Wm_pr[i];
        as += x * Ws_pr[i];
    }
    am = warp_sum(am); as = warp_sum(as);
    if (lane == 0) { red[w] = am; red[8 + w] = as; }
    __syncthreads();
    if (t == 0) {
        float m = 0.0f, s = 0.0f;
#pragma unroll
        for (int q = 0; q < 8; q++) { m += red[q]; s += red[8 + q]; }
        float p = sigm(m + bm_pr[0]) * sigm(s + bs_pr[0]);
        zpres_out[(size_t)n * KS + k] = p * zpres_last[(size_t)n * KS + k];
    }
}

// ---------------- host ----------------
extern "C" void kernel_launch(void* const* d_in, const int* in_sizes, int n_in,
                              void* d_out, int out_size) {
    const float* img         = (const float*)d_in[0];
    const float* zwhat_last  = (const float*)d_in[1];
    const float* zwhere_last = (const float*)d_in[2];
    const float* zpres_last  = (const float*)d_in[3];
    const float* hidden_last = (const float*)d_in[4];
    const float* W_loca = (const float*)d_in[5];
    const float* b_loca = (const float*)d_in[6];
    const float* Wg     = (const float*)d_in[7];
    const float* bg     = (const float*)d_in[8];
    const float* Wih_rel = (const float*)d_in[9];
    const float* Whh_rel = (const float*)d_in[10];
    const float* bih_rel = (const float*)d_in[11];
    const float* bhh_rel = (const float*)d_in[12];
    const float* Wih_tem = (const float*)d_in[13];
    const float* Whh_tem = (const float*)d_in[14];
    const float* bih_tem = (const float*)d_in[15];
    const float* bhh_tem = (const float*)d_in[16];
    const float* Wm_wh = (const float*)d_in[17];
    const float* bm_wh = (const float*)d_in[18];
    const float* Wm_wt = (const float*)d_in[21];
    const float* bm_wt = (const float*)d_in[22];
    const float* Wm_pr = (const float*)d_in[25];
    const float* bm_pr = (const float*)d_in[26];
    const float* Ws_pr = (const float*)d_in[27];
    const float* bs_pr = (const float*)d_in[28];

    float* out = (float*)d_out;
    float* zwhat_out  = out;
    float* zwhere_out = out + (size_t)NB * KS * 50;
    float* zpres_out  = zwhere_out + (size_t)NB * KS * 3;
    float* htemp_out  = zpres_out + (size_t)NB * KS * 1;

    void *pG1h, *pG1l, *pXrh, *pXrl, *pXth, *pXtl, *pGates;
    void *pWrh, *pWrl, *pWth, *pWtl, *pWgh, *pWgl, *pBrel, *pBtem;
    cudaGetSymbolAddress(&pG1h, d_G1h); cudaGetSymbolAddress(&pG1l, d_G1l);
    cudaGetSymbolAddress(&pXrh, d_xrh); cudaGetSymbolAddress(&pXrl, d_xrl);
    cudaGetSymbolAddress(&pXth, d_xth); cudaGetSymbolAddress(&pXtl, d_xtl);
    cudaGetSymbolAddress(&pGates, d_gates);
    cudaGetSymbolAddress(&pWrh, d_Wrh); cudaGetSymbolAddress(&pWrl, d_Wrl);
    cudaGetSymbolAddress(&pWth, d_Wth); cudaGetSymbolAddress(&pWtl, d_Wtl);
    cudaGetSymbolAddress(&pWgh, d_Wgh); cudaGetSymbolAddress(&pWgl, d_Wgl);
    cudaGetSymbolAddress(&pBrel, d_brel); cudaGetSymbolAddress(&pBtem, d_btem);

    cudaFuncSetAttribute(hmma_gemm<0>, cudaFuncAttributeMaxDynamicSharedMemorySize, SMEM_REQ);
    cudaFuncSetAttribute(hmma_gemm<1>, cudaFuncAttributeMaxDynamicSharedMemorySize, SMEM_REQ);

    prep_kernel<<<2048, 256>>>(Wih_rel, Whh_rel, bih_rel, bhh_rel,
                               Wih_tem, Whh_tem, bih_tem, bhh_tem, Wg);
    staticpack_kernel<<<NB * KS, 256>>>(img, hidden_last, zwhere_last, zwhat_last,
                                        W_loca, b_loca);
    // enc GEMM: M=16384, N=100(pad 128), K=2560 -> xrel[:,0:100] as hi/lo
    {
        dim3 grid(1, NB * KS / 128);
        hmma_gemm<1><<<grid, 256, SMEM_REQ>>>(
            (const __nv_bfloat16*)pG1h, (const __nv_bfloat16*)pG1l, KENC,
            (const __nv_bfloat16*)pWgh, (const __nv_bfloat16*)pWgl, KENC,
            bg, nullptr, (__nv_bfloat16*)pXrh, (__nv_bfloat16*)pXrl, KREL,
            KENC, 100);
    }
    for (int k = 0; k < KS; k++) {
        recpack_kernel<<<NB, 256>>>(zwhere_out, zwhat_out, k);
        // rel gates: M=2048 (rows n*8+k), N=1024, K=768
        {
            dim3 grid(NGATE / 128, NB / 128);
            hmma_gemm<0><<<grid, 256, SMEM_REQ>>>(
                (const __nv_bfloat16*)pXrh + (size_t)k * KREL,
                (const __nv_bfloat16*)pXrl + (size_t)k * KREL, KS * KREL,
                (const __nv_bfloat16*)pWrh, (const __nv_bfloat16*)pWrl, KREL,
                (const float*)pBrel, (float*)pGates, nullptr, nullptr, NGATE,
                KREL, NGATE);
        }
        relglimpse2_kernel<<<NB, 256>>>(img, hidden_last, zwhere_last, zwhat_last,
                                        Wm_wh, bm_wh, zwhat_out, zwhere_out, k);
        // tem gates: M=2048, N=1024, K=3136
        {
            dim3 grid(NGATE / 128, NB / 128);
            hmma_gemm<0><<<grid, 256, SMEM_REQ>>>(
                (const __nv_bfloat16*)pXth, (const __nv_bfloat16*)pXtl, KTEM,
                (const __nv_bfloat16*)pWth, (const __nv_bfloat16*)pWtl, KTEM,
                (const float*)pBtem, (float*)pGates, nullptr, nullptr, NGATE,
                KTEM, NGATE);
        }
        head_kernel<<<NB, 256>>>(zwhat_last, zpres_last, Wm_wt, bm_wt,
                                 Wm_pr, bm_pr, Ws_pr, bs_pr,
                                 zwhere_out, zwhat_out, zpres_out, htemp_out, k);
    }
}